// round 9
// baseline (speedup 1.0000x reference)
#include <cuda_runtime.h>

#define SZ   256          // image size
#define NT   256          // number of triangles
#define QSTRIDE 5         // float4 per triangle record (80B: kills bank conflicts)

// Per-triangle record layout (float4 index, stride 5, 80 B):
//  q0 : pAB edge: ax(=v1x), ay(=v1y), dy(=v0y-v1y), dx(=v0x-v1x)
//  q1 : pCB edge: ax(=v2x), ay(=v2y), dy(=v1y-v2y), dx(=v1x-v2x)
//  q2 : pCA edge: ax(=v0x), ay(=v0y), dy(=v2y-v0y), dx(=v2x-v0x)
//  q3 : invw, z0, z1, z2
//  q4 : pad (written zero)
// Slot NT is an all-zero "null" record: prod==0 -> never taken. The list is
// padded with null entries so offset prefetch needs no bounds check.
//
// UV data is NOT staged: the winning triangle's uvs are fetched from global
// in the tail (once per pixel) and transformed there — identical arithmetic.
//
// Block: 256 threads = 64 pixels (8x8 tile) x 4 triangle slices.
// Warp layout: lane = slice*8 + pixCol, warp index = pixRow within tile.
// Grid: (32, 32) = 1024 blocks; 7 CTAs/SM -> 1036 resident -> SINGLE WAVE
// (the round-6 6-CTA config left a 136-block straggler tail).
//
// The z-buffer scan reduces to an argmax over covering triangles with ties
// broken by larger triangle index ('inside' => all barycentric weights > 0 =>
// z is a convex combination of vertex z's => z >= global zmin, so the zbuf
// init never matters for covered pixels). Argmax is order-independent:
// the candidate list needs NO ordering (tie-break uses the stored offset,
// monotone in triangle index), and slices merge by shuffle reduction.
//
// Edge culling: each edge function e(p) is affine in p, so over the tile
// rectangle its max is at a corner. If any edge's corner-max <= -1e-5
// (rounding of O(1) fp32 values is < 1e-6), no pixel in the tile can have
// all three edge values strictly positive -> triangle cannot win any pixel.
//
// NOTE: the inside-test arithmetic form (px-ax)*dy-(py-ay)*dx must match the
// reference exactly — refactoring it flips boundary pixels and fails 1e-3.
__global__ __launch_bounds__(256, 7)
void render_kernel(const float* __restrict__ tris,
                   const float* __restrict__ uvs,
                   const float* __restrict__ uvmap,
                   float* __restrict__ out) {
    __shared__ __align__(16) float4 s_q[(NT + 1) * QSTRIDE];  // ~20.6 KB
    __shared__ unsigned short s_list[NT + 8];                 // quad offsets (tt*5)
    __shared__ int s_cnt;

    int tid   = threadIdx.x;
    int lane  = tid & 31;
    int warp  = tid >> 5;
    int slice = lane >> 3;        // 0..3
    int pcol  = lane & 7;         // 0..7

    const float d = 2.0f / 255.0f;

    if (tid == 0) s_cnt = 0;
    if (tid < QSTRIDE)            // null record (never wins: prod == 0)
        s_q[NT * QSTRIDE + tid] = make_float4(0.0f, 0.0f, 0.0f, 0.0f);

    // Tile corner coordinates, computed with the exact per-pixel formula.
    int jx0 = blockIdx.x * 8, jx1 = jx0 + 7;
    int iy0 = blockIdx.y * 8, iy1 = iy0 + 7;
    float cx0 = -1.0f + (float)jx0 * d;   // px at pcol=0
    float cx1 = -1.0f + (float)jx1 * d;   // px at pcol=7
    float cy0 =  1.0f - (float)iy0 * d;   // py at row=0 (max y)
    float cy1 =  1.0f - (float)iy1 * d;   // py at row=7 (min y)

    // ---- Fused prep: thread t builds triangle t's record in shared ----
    bool keep;
    {
        const float* T = tris + tid * 9;
        float v0x = __ldg(T + 0), v0y = __ldg(T + 1), v0z = __ldg(T + 2);
        float v1x = __ldg(T + 3), v1y = __ldg(T + 4), v1z = __ldg(T + 5);
        float v2x = __ldg(T + 6), v2y = __ldg(T + 7), v2z = __ldg(T + 8);

        float w = (v1x - v0x) * (v2y - v0y) - (v1y - v0y) * (v2x - v0x);
        bool valid = (w >= 1e-9f);
        float ws = valid ? w : 1.0f;
        float invw = 1.0f / ws;

        float4* Q = s_q + tid * QSTRIDE;
        Q[0] = make_float4(v1x, v1y, v0y - v1y, v0x - v1x);
        Q[1] = make_float4(v2x, v2y, v1y - v2y, v1x - v2x);
        Q[2] = make_float4(v0x, v0y, v2y - v0y, v2x - v0x);
        Q[3] = make_float4(invw, v0z, v1z, v2z);
        Q[4] = make_float4(0.0f, 0.0f, 0.0f, 0.0f);

        // Edge corner-max cull: e = (cx-ax)*dy - (cy-ay)*dx is separable,
        // max = max_x[(cx-ax)*dy] + max_y[-(cy-ay)*dx].
        #define EDGE_MAX(ax, ay, dy, dx) \
            (fmaxf((cx0 - (ax)) * (dy), (cx1 - (ax)) * (dy)) + \
             fmaxf(-((cy0 - (ay)) * (dx)), -((cy1 - (ay)) * (dx))))
        float mAB = EDGE_MAX(v1x, v1y, v0y - v1y, v0x - v1x);
        float mCB = EDGE_MAX(v2x, v2y, v1y - v2y, v1x - v2x);
        float mCA = EDGE_MAX(v0x, v0y, v2y - v0y, v2x - v0x);
        #undef EDGE_MAX

        keep = valid && (mAB > -1e-5f) && (mCB > -1e-5f) && (mCA > -1e-5f);
    }

    // Unordered compaction: ballot + one shared atomic per warp.
    __syncthreads();
    unsigned mask = __ballot_sync(0xffffffffu, keep);
    int base = 0;
    if (lane == 0 && mask) base = atomicAdd(&s_cnt, __popc(mask));
    base = __shfl_sync(0xffffffffu, base, 0);
    if (keep)
        s_list[base + __popc(mask & ((1u << lane) - 1u))] =
            (unsigned short)(tid * QSTRIDE);   // quad offset; monotone in tid
    __syncthreads();
    int cnt = s_cnt;
    if (tid < 8) s_list[cnt + tid] = (unsigned short)(NT * QSTRIDE); // null pad
    __syncthreads();

    // Pixel coordinates: pts[i][j] = (lin[j], lin[255-i]), lin[k] = -1 + k*2/255
    int j = jx0 + pcol;
    int i = iy0 + warp;
    float px = -1.0f + (float)j * d;
    float py =  1.0f - (float)i * d;

    // Each slice scans every 4th surviving triangle. Branch-free updates;
    // tie-break (z equal) -> larger stored offset == larger triangle index.
    // Next list offset is prefetched one iteration ahead (list is null-padded
    // so k+4 is always a valid read).
    float zb  = -3.402823466e+38f;
    float w1s = 0.0f, w2s = 0.0f;
    int   bi  = -1;

    int off_c = s_list[slice];
    for (int k = slice; k < cnt; k += 4) {
        int off_n = s_list[k + 4];

        float4 q0 = s_q[off_c], q1 = s_q[off_c + 1],
               q2 = s_q[off_c + 2], q3 = s_q[off_c + 3];

        float pAB = (px - q0.x) * q0.z - (py - q0.y) * q0.w;
        float pCB = (px - q1.x) * q1.z - (py - q1.y) * q1.w;
        float pCA = (px - q2.x) * q2.z - (py - q2.y) * q2.w;

        float prod = fmaxf(pAB, 0.0f) * fmaxf(pCB, 0.0f) * fmaxf(pCA, 0.0f);

        float w1 = pCB * q3.x;
        float w2 = pCA * q3.x;
        float w3 = 1.0f - w1 - w2;
        float z  = w1 * q3.y + w2 * q3.z + w3 * q3.w;

        bool take = (prod > 0.0f) &&
                    ((z > zb) || ((z == zb) && (off_c > bi)));
        zb  = take ? z     : zb;
        bi  = take ? off_c : bi;
        w1s = take ? w1    : w1s;
        w2s = take ? w2    : w2s;

        off_c = off_n;
    }

    // Merge the 4 slices of each pixel: (z, off) max, ties -> larger off.
    #pragma unroll
    for (int off = 8; off < 32; off <<= 1) {
        float oz = __shfl_down_sync(0xffffffffu, zb, off);
        int   oi = __shfl_down_sync(0xffffffffu, bi, off);
        float o1 = __shfl_down_sync(0xffffffffu, w1s, off);
        float o2 = __shfl_down_sync(0xffffffffu, w2s, off);
        bool take = (oz > zb) || ((oz == zb) && (oi > bi));
        if (take) { zb = oz; bi = oi; w1s = o1; w2s = o2; }
    }

    if (slice == 0) {
        // Deferred UV interpolation + bilinear texture sample (winner only)
        float r = 0.0f, g = 0.0f, b = 0.0f, a = 0.0f;
        if (bi >= 0) {
            a = 1.0f;
            const float* U = uvs + (bi / QSTRIDE) * 6;   // bi = tt*QSTRIDE
            float u0 = __ldg(U + 0) * 2.0f - 1.0f, v0 = __ldg(U + 1) * 2.0f - 1.0f;
            float u1 = __ldg(U + 2) * 2.0f - 1.0f, v1 = __ldg(U + 3) * 2.0f - 1.0f;
            float u2 = __ldg(U + 4) * 2.0f - 1.0f, v2 = __ldg(U + 5) * 2.0f - 1.0f;
            float w3 = 1.0f - w1s - w2s;
            float uu = w1s * u0 + w2s * u1 + w3 * u2;
            float vv = w1s * v0 + w2s * v1 + w3 * v2;

            float x = (uu + 1.0f) * 0.5f * 1023.0f;
            float y = (vv + 1.0f) * 0.5f * 1023.0f;
            float x0f = floorf(x);
            float y0f = floorf(y);
            float wx = x - x0f;
            float wy = y - y0f;
            #pragma unroll
            for (int cy = 0; cy < 2; cy++) {
                #pragma unroll
                for (int cx = 0; cx < 2; cx++) {
                    float ix = x0f + (float)cx;
                    float iy = y0f + (float)cy;
                    bool inb = (ix >= 0.0f) && (ix <= 1023.0f) &&
                               (iy >= 0.0f) && (iy <= 1023.0f);
                    if (inb) {
                        int ii = (int)ix;
                        int jj = (int)iy;
                        float wgt = (cx ? wx : 1.0f - wx) * (cy ? wy : 1.0f - wy);
                        int toff = jj * 1024 + ii;
                        r += __ldg(uvmap + toff) * wgt;
                        g += __ldg(uvmap + 1048576 + toff) * wgt;
                        b += __ldg(uvmap + 2097152 + toff) * wgt;
                    }
                }
            }
        }

        int pix = i * SZ + j;
        out[pix]              = r;
        out[65536 + pix]      = g;
        out[2 * 65536 + pix]  = b;
        out[3 * 65536 + pix]  = a;
    }
}

extern "C" void kernel_launch(void* const* d_in, const int* in_sizes, int n_in,
                              void* d_out, int out_size) {
    const float* tris  = (const float*)d_in[0];   // (256,3,3)
    const float* uvs   = (const float*)d_in[1];   // (256,3,2)
    const float* uvmap = (const float*)d_in[2];   // (3,1024,1024)
    float* out = (float*)d_out;                   // (4,256,256)

    dim3 block(256);
    dim3 grid(SZ / 8, SZ / 8);
    render_kernel<<<grid, block>>>(tris, uvs, uvmap, out);
}

// round 10
// speedup vs baseline: 1.0507x; 1.0507x over previous
#include <cuda_runtime.h>

#define SZ   256          // image size
#define NT   256          // number of triangles
#define QSTRIDE 5         // float4 per triangle record (80B: kills bank conflicts)

// Per-triangle record layout (float4 index, stride 5, 80 B):
//  q0 : pAB edge: ax(=v1x), ay(=v1y), dy(=v0y-v1y), dx(=v0x-v1x)
//  q1 : pCB edge: ax(=v2x), ay(=v2y), dy(=v1y-v2y), dx(=v1x-v2x)
//  q2 : pCA edge: ax(=v0x), ay(=v0y), dy(=v2y-v0y), dx(=v2x-v0x)
//  q3 : invw, z0, z1, z2
//  q4 : pad (written zero)
// Slot NT is an all-zero "null" record: prod==0 -> never taken. Used to pad
// the candidate list so the x2-unrolled loop needs no tail guard.
//
// Raw tris are STAGED through shared memory with coalesced float4 loads:
// the naive per-thread tris[t*9+c] pattern costs ~650 L1 wavefronts/block
// (~2x the whole main loop's LDS traffic); staging cuts it to ~18.
//
// UV data is NOT staged: the winning triangle's uvs are fetched from global
// in the tail (once per pixel) and transformed there — identical arithmetic.
//
// Block: 256 threads = 64 pixels (8x8 tile) x 4 triangle slices.
// Warp layout: lane = slice*8 + pixCol, warp index = pixRow within tile.
// Grid: (32, 32) = 1024 blocks at 6 CTAs/SM (round-6 config, best measured).
//
// The z-buffer scan reduces to an argmax over covering triangles with ties
// broken by larger triangle index ('inside' => all barycentric weights > 0 =>
// z is a convex combination of vertex z's => z >= global zmin, so the zbuf
// init never matters for covered pixels). Argmax is order-independent:
// the candidate list needs NO ordering (tie-break uses the stored offset,
// monotone in triangle index), and slices merge by shuffle reduction.
//
// Edge culling: each edge function e(p) is affine in p, so over the tile
// rectangle its max is at a corner. If any edge's corner-max <= -1e-5
// (rounding of O(1) fp32 values is < 1e-6), no pixel in the tile can have
// all three edge values strictly positive -> triangle cannot win any pixel.
//
// NOTE: the inside-test arithmetic form (px-ax)*dy-(py-ay)*dx must match the
// reference exactly — refactoring it flips boundary pixels and fails 1e-3.
__global__ __launch_bounds__(256, 6)
void render_kernel(const float* __restrict__ tris,
                   const float* __restrict__ uvs,
                   const float* __restrict__ uvmap,
                   float* __restrict__ out) {
    __shared__ __align__(16) float4 s_q[(NT + 1) * QSTRIDE];  // ~20.6 KB
    __shared__ __align__(16) float s_tris[NT * 9];            // 9 KB raw stage
    __shared__ unsigned short s_list[NT + 8];                 // quad offsets (tt*5)
    __shared__ int s_cnt;

    int tid   = threadIdx.x;
    int lane  = tid & 31;
    int warp  = tid >> 5;
    int slice = lane >> 3;        // 0..3
    int pcol  = lane & 7;         // 0..7

    const float d = 2.0f / 255.0f;

    if (tid == 0) s_cnt = 0;
    if (tid < QSTRIDE)            // null record (never wins: prod == 0)
        s_q[NT * QSTRIDE + tid] = make_float4(0.0f, 0.0f, 0.0f, 0.0f);

    // Coalesced stage of raw tris into shared (576 float4 = 2304 floats).
    {
        const float4* src = (const float4*)tris;
        float4* dst = (float4*)s_tris;
        #pragma unroll
        for (int k = tid; k < NT * 9 / 4; k += 256) dst[k] = __ldg(src + k);
    }
    __syncthreads();

    // Tile corner coordinates, computed with the exact per-pixel formula.
    int jx0 = blockIdx.x * 8, jx1 = jx0 + 7;
    int iy0 = blockIdx.y * 8, iy1 = iy0 + 7;
    float cx0 = -1.0f + (float)jx0 * d;   // px at pcol=0
    float cx1 = -1.0f + (float)jx1 * d;   // px at pcol=7
    float cy0 =  1.0f - (float)iy0 * d;   // py at row=0 (max y)
    float cy1 =  1.0f - (float)iy1 * d;   // py at row=7 (min y)

    // ---- Fused prep: thread t builds triangle t's record in shared ----
    // (stride-9 shared reads: 9 coprime with 32 -> bank-conflict-free)
    bool keep;
    {
        const float* T = s_tris + tid * 9;
        float v0x = T[0], v0y = T[1], v0z = T[2];
        float v1x = T[3], v1y = T[4], v1z = T[5];
        float v2x = T[6], v2y = T[7], v2z = T[8];

        float w = (v1x - v0x) * (v2y - v0y) - (v1y - v0y) * (v2x - v0x);
        bool valid = (w >= 1e-9f);
        float ws = valid ? w : 1.0f;
        float invw = 1.0f / ws;

        float4* Q = s_q + tid * QSTRIDE;
        Q[0] = make_float4(v1x, v1y, v0y - v1y, v0x - v1x);
        Q[1] = make_float4(v2x, v2y, v1y - v2y, v1x - v2x);
        Q[2] = make_float4(v0x, v0y, v2y - v0y, v2x - v0x);
        Q[3] = make_float4(invw, v0z, v1z, v2z);
        Q[4] = make_float4(0.0f, 0.0f, 0.0f, 0.0f);

        // Edge corner-max cull: e = (cx-ax)*dy - (cy-ay)*dx is separable,
        // max = max_x[(cx-ax)*dy] + max_y[-(cy-ay)*dx].
        #define EDGE_MAX(ax, ay, dy, dx) \
            (fmaxf((cx0 - (ax)) * (dy), (cx1 - (ax)) * (dy)) + \
             fmaxf(-((cy0 - (ay)) * (dx)), -((cy1 - (ay)) * (dx))))
        float mAB = EDGE_MAX(v1x, v1y, v0y - v1y, v0x - v1x);
        float mCB = EDGE_MAX(v2x, v2y, v1y - v2y, v1x - v2x);
        float mCA = EDGE_MAX(v0x, v0y, v2y - v0y, v2x - v0x);
        #undef EDGE_MAX

        keep = valid && (mAB > -1e-5f) && (mCB > -1e-5f) && (mCA > -1e-5f);
    }

    // Unordered compaction: ballot + one shared atomic per warp.
    unsigned mask = __ballot_sync(0xffffffffu, keep);
    int base = 0;
    if (lane == 0 && mask) base = atomicAdd(&s_cnt, __popc(mask));
    base = __shfl_sync(0xffffffffu, base, 0);
    if (keep)
        s_list[base + __popc(mask & ((1u << lane) - 1u))] =
            (unsigned short)(tid * QSTRIDE);   // quad offset; monotone in tid
    __syncthreads();
    int cnt = s_cnt;
    if (tid < 8) s_list[cnt + tid] = (unsigned short)(NT * QSTRIDE); // null pad
    __syncthreads();

    // Pixel coordinates: pts[i][j] = (lin[j], lin[255-i]), lin[k] = -1 + k*2/255
    int j = jx0 + pcol;
    int i = iy0 + warp;
    float px = -1.0f + (float)j * d;
    float py =  1.0f - (float)i * d;

    // Each slice scans every 4th surviving triangle, two per loop iteration
    // (second may be the null record -> never taken). Branch-free updates;
    // tie-break (z equal) -> larger stored offset == larger triangle index.
    float zb  = -3.402823466e+38f;
    float w1s = 0.0f, w2s = 0.0f;
    int   bi  = -1;

    #define EVAL(OFF)                                                        \
    {                                                                        \
        int off = (OFF);                                                     \
        float4 q0 = s_q[off], q1 = s_q[off + 1],                             \
               q2 = s_q[off + 2], q3 = s_q[off + 3];                         \
        float pAB = (px - q0.x) * q0.z - (py - q0.y) * q0.w;                 \
        float pCB = (px - q1.x) * q1.z - (py - q1.y) * q1.w;                 \
        float pCA = (px - q2.x) * q2.z - (py - q2.y) * q2.w;                 \
        float prod = fmaxf(pAB, 0.0f) * fmaxf(pCB, 0.0f) * fmaxf(pCA, 0.0f); \
        float w1 = pCB * q3.x;                                               \
        float w2 = pCA * q3.x;                                               \
        float w3 = 1.0f - w1 - w2;                                           \
        float z  = w1 * q3.y + w2 * q3.z + w3 * q3.w;                        \
        bool take = (prod > 0.0f) &&                                         \
                    ((z > zb) || ((z == zb) && (off > bi)));                 \
        zb  = take ? z   : zb;                                               \
        bi  = take ? off : bi;                                               \
        w1s = take ? w1  : w1s;                                              \
        w2s = take ? w2  : w2s;                                              \
    }

    for (int k = slice; k < cnt; k += 8) {
        int offA = s_list[k];
        int offB = s_list[k + 4];
        EVAL(offA);
        EVAL(offB);
    }
    #undef EVAL

    // Merge the 4 slices of each pixel: (z, off) max, ties -> larger off.
    #pragma unroll
    for (int off = 8; off < 32; off <<= 1) {
        float oz = __shfl_down_sync(0xffffffffu, zb, off);
        int   oi = __shfl_down_sync(0xffffffffu, bi, off);
        float o1 = __shfl_down_sync(0xffffffffu, w1s, off);
        float o2 = __shfl_down_sync(0xffffffffu, w2s, off);
        bool take = (oz > zb) || ((oz == zb) && (oi > bi));
        if (take) { zb = oz; bi = oi; w1s = o1; w2s = o2; }
    }

    if (slice == 0) {
        // Deferred UV interpolation + bilinear texture sample (winner only)
        float r = 0.0f, g = 0.0f, b = 0.0f, a = 0.0f;
        if (bi >= 0) {
            a = 1.0f;
            const float* U = uvs + (bi / QSTRIDE) * 6;   // bi = tt*QSTRIDE
            float u0 = __ldg(U + 0) * 2.0f - 1.0f, v0 = __ldg(U + 1) * 2.0f - 1.0f;
            float u1 = __ldg(U + 2) * 2.0f - 1.0f, v1 = __ldg(U + 3) * 2.0f - 1.0f;
            float u2 = __ldg(U + 4) * 2.0f - 1.0f, v2 = __ldg(U + 5) * 2.0f - 1.0f;
            float w3 = 1.0f - w1s - w2s;
            float uu = w1s * u0 + w2s * u1 + w3 * u2;
            float vv = w1s * v0 + w2s * v1 + w3 * v2;

            float x = (uu + 1.0f) * 0.5f * 1023.0f;
            float y = (vv + 1.0f) * 0.5f * 1023.0f;
            float x0f = floorf(x);
            float y0f = floorf(y);
            float wx = x - x0f;
            float wy = y - y0f;
            #pragma unroll
            for (int cy = 0; cy < 2; cy++) {
                #pragma unroll
                for (int cx = 0; cx < 2; cx++) {
                    float ix = x0f + (float)cx;
                    float iy = y0f + (float)cy;
                    bool inb = (ix >= 0.0f) && (ix <= 1023.0f) &&
                               (iy >= 0.0f) && (iy <= 1023.0f);
                    if (inb) {
                        int ii = (int)ix;
                        int jj = (int)iy;
                        float wgt = (cx ? wx : 1.0f - wx) * (cy ? wy : 1.0f - wy);
                        int toff = jj * 1024 + ii;
                        r += __ldg(uvmap + toff) * wgt;
                        g += __ldg(uvmap + 1048576 + toff) * wgt;
                        b += __ldg(uvmap + 2097152 + toff) * wgt;
                    }
                }
            }
        }

        int pix = i * SZ + j;
        out[pix]              = r;
        out[65536 + pix]      = g;
        out[2 * 65536 + pix]  = b;
        out[3 * 65536 + pix]  = a;
    }
}

extern "C" void kernel_launch(void* const* d_in, const int* in_sizes, int n_in,
                              void* d_out, int out_size) {
    const float* tris  = (const float*)d_in[0];   // (256,3,3)
    const float* uvs   = (const float*)d_in[1];   // (256,3,2)
    const float* uvmap = (const float*)d_in[2];   // (3,1024,1024)
    float* out = (float*)d_out;                   // (4,256,256)

    dim3 block(256);
    dim3 grid(SZ / 8, SZ / 8);
    render_kernel<<<grid, block>>>(tris, uvs, uvmap, out);
}